// round 6
// baseline (speedup 1.0000x reference)
#include <cuda_runtime.h>
#include <math.h>
#include <stdint.h>

#define Nn 8192
#define IN_FEAT 128
#define OUTF 64
#define LALPHA 0.2f
#define NEG_BIG (-9e15f)

#define BI 32              // rows per tile
#define BJ 128             // j-chunk
#define JS 2               // j-split CTAs per tile
#define NCH ((Nn/JS)/BJ)   // 32 chunks per CTA
#define TPB 256
#define HST 68             // hs stride: 2bk*68%32={0,8,16,24} -> conflict-free B LDS
#define RST 68             // reduction stride: row*68 % 4 == 0 -> float4-safe
#define SMEM_BYTES (BJ*HST*4)   // 34816 B = 8704 floats -> 3 CTAs/SM

// Scratch (device globals — no allocation allowed)
__device__ float g_htf[Nn*OUTF];              // h pre-rounded to tf32
__device__ float g_si[Nn];
__device__ float g_sj[Nn];
__device__ unsigned g_sjmax_enc;              // order-preserving encoding
__device__ float g_pacc[(Nn/BI)*JS*BI*OUTF];  // partial P@H per split CTA
__device__ float g_pl[(Nn/BI)*JS*BI];         // partial row sums

__device__ __forceinline__ uint32_t f2tf(float x) {
    uint32_t r;
    asm("cvt.rna.tf32.f32 %0, %1;" : "=r"(r) : "f"(x));
    return r;
}
__device__ __forceinline__ unsigned enc_f(float x) {
    unsigned u = __float_as_uint(x);
    return (u & 0x80000000u) ? ~u : (u | 0x80000000u);
}
__device__ __forceinline__ float dec_f(unsigned u) {
    return __uint_as_float((u & 0x80000000u) ? (u & 0x7FFFFFFFu) : ~u);
}
__device__ __forceinline__ void mma_tf32(float* c,
                                         uint32_t a0, uint32_t a1, uint32_t a2, uint32_t a3,
                                         uint32_t b0, uint32_t b1) {
    asm volatile(
        "mma.sync.aligned.m16n8k8.row.col.f32.tf32.tf32.f32 "
        "{%0,%1,%2,%3}, {%4,%5,%6,%7}, {%8,%9}, {%0,%1,%2,%3};"
        : "+f"(c[0]), "+f"(c[1]), "+f"(c[2]), "+f"(c[3])
        : "r"(a0), "r"(a1), "r"(a2), "r"(a3), "r"(b0), "r"(b1));
}

// ---------------------------------------------------------------------------
// K1: h = features @ W.T (stored tf32-rounded), fused s_i/s_j + max(s_j)
// ---------------------------------------------------------------------------
__global__ void __launch_bounds__(256) k_h(const float* __restrict__ feat,
                                           const float* __restrict__ W,
                                           const float* __restrict__ avec) {
    __shared__ float Wt[IN_FEAT][OUTF];
    __shared__ float sjred[32];
    int t = threadIdx.x;
#pragma unroll
    for (int w = 0; w < 8; w++) {
        int idx = t + 256 * w;
        int f   = idx >> 5;
        int c4  = idx & 31;
        float4 wv = ((const float4*)W)[idx];
        int k = c4 * 4;
        Wt[k + 0][f] = wv.x;
        Wt[k + 1][f] = wv.y;
        Wt[k + 2][f] = wv.z;
        Wt[k + 3][f] = wv.w;
    }
    __syncthreads();

    int il = t >> 3;
    int fo = t & 7;
    int i  = blockIdx.x * 32 + il;
    const float4* fr = (const float4*)(feat + (size_t)i * IN_FEAT);

    float acc[8];
#pragma unroll
    for (int c = 0; c < 8; c++) acc[c] = 0.f;

#pragma unroll
    for (int kk = 0; kk < 32; kk++) {
        float4 fv = fr[kk];
#pragma unroll
        for (int c = 0; c < 4; c++) {
            float fc = (c == 0) ? fv.x : (c == 1) ? fv.y : (c == 2) ? fv.z : fv.w;
            int k = kk * 4 + c;
            float4 w0 = *(const float4*)&Wt[k][fo * 8];
            float4 w1 = *(const float4*)&Wt[k][fo * 8 + 4];
            acc[0] += fc * w0.x; acc[1] += fc * w0.y;
            acc[2] += fc * w0.z; acc[3] += fc * w0.w;
            acc[4] += fc * w1.x; acc[5] += fc * w1.y;
            acc[6] += fc * w1.z; acc[7] += fc * w1.w;
        }
    }
    uint4 o0, o1;
    o0.x = f2tf(acc[0]); o0.y = f2tf(acc[1]); o0.z = f2tf(acc[2]); o0.w = f2tf(acc[3]);
    o1.x = f2tf(acc[4]); o1.y = f2tf(acc[5]); o1.z = f2tf(acc[6]); o1.w = f2tf(acc[7]);
    *(uint4*)(g_htf + (size_t)i * OUTF + fo * 8)     = o0;
    *(uint4*)(g_htf + (size_t)i * OUTF + fo * 8 + 4) = o1;

    float sx = 0.f, sy = 0.f;
#pragma unroll
    for (int c = 0; c < 8; c++) {
        sx += acc[c] * avec[fo * 8 + c];
        sy += acc[c] * avec[OUTF + fo * 8 + c];
    }
#pragma unroll
    for (int o = 4; o > 0; o >>= 1) {
        sx += __shfl_down_sync(0xffffffffu, sx, o, 8);
        sy += __shfl_down_sync(0xffffffffu, sy, o, 8);
    }
    if (fo == 0) {
        g_si[i] = sx;
        g_sj[i] = sy;
        sjred[il] = sy;
    }
    __syncthreads();
    if (t == 0) {
        float m = sjred[0];
#pragma unroll
        for (int c = 1; c < 32; c++) m = fmaxf(m, sjred[c]);
        atomicMax(&g_sjmax_enc, enc_f(m));   // idempotent across replays
    }
}

// ---------------------------------------------------------------------------
// K2: scores computed directly into mma A-frags (no ps smem), warps = 2m x 4k,
//     k-permuted so adjacency loads are contiguous float2. 2 syncs/chunk.
// Grid: 512 CTAs, 3 CTAs/SM.
// ---------------------------------------------------------------------------
__global__ void __launch_bounds__(TPB, 3) k_main(const float* __restrict__ geo,
                                                 const float* __restrict__ sem) {
    extern __shared__ float smem[];
    float* hs = smem;                       // [BJ][HST] tf32 h chunk
    __shared__ float lred[128];             // [4 k-warps][32 rows]

    int t    = threadIdx.x;
    int bid  = blockIdx.x;
    int tile = bid >> 1;
    int half = bid & 1;
    int i0   = tile * BI;
    int jbase = half * (Nn / JS);
    int lane = t & 31;
    int warp = t >> 5;
    int wm = warp & 1, wk = warp >> 1;      // m-group, k-slice
    int m0 = wm * 16;
    int ar = lane >> 2, ac = lane & 3;      // A-frag / C-frag row,col
    int bk = lane & 3,  bn = lane >> 2;     // B-frag

    int r0 = i0 + m0 + ar, r1 = r0 + 8;
    float sjm = dec_f(g_sjmax_enc);
    float si0 = g_si[r0], si1 = g_si[r1];
    float mr0 = fmaxf(0.f, 2.f * (si0 + sjm));
    float mr1 = fmaxf(0.f, 2.f * (si1 + sjm));
    float l0 = 0.f, l1 = 0.f;

    // this thread's adjacency column pairs: j = jbase + wk*32 + ks*8 + 2*ac
    int co = wk * 32 + 2 * ac;
    const float2* gr0 = (const float2*)(geo + (size_t)r0 * Nn + jbase) + (co >> 1);
    const float2* gr1 = (const float2*)(geo + (size_t)r1 * Nn + jbase) + (co >> 1);
    const float2* sr0 = (const float2*)(sem + (size_t)r0 * Nn + jbase) + (co >> 1);
    const float2* sr1 = (const float2*)(sem + (size_t)r1 * Nn + jbase) + (co >> 1);
    const float2* sjp = (const float2*)(g_sj + jbase) + (co >> 1);

    int jr = t >> 4, f4 = t & 15;           // staging mapping

    float acc[8][4];
#pragma unroll
    for (int a = 0; a < 8; a++)
#pragma unroll
        for (int b = 0; b < 4; b++) acc[a][b] = 0.f;

    for (int ci = 0; ci < NCH; ci++) {
        __syncthreads();                    // hs free (prev GEMM done)

        // ---- stage h chunk (tf32 already) ----
        int jrow = jbase + ci * BJ;
#pragma unroll
        for (int it = 0; it < 8; it++) {
            int j = jr + 16 * it;
            float4 hv = *(const float4*)(g_htf + (size_t)(jrow + j) * OUTF + f4 * 4);
            *(float4*)(hs + j * HST + f4 * 4) = hv;
        }

        // ---- scores directly into A-frags (no smem) ----
        uint32_t atf[4][4];
        int cb2 = ci * (BJ / 2);            // float2 chunk base
#pragma unroll
        for (int hb = 0; hb < 2; hb++) {
            float2 gv0[2], gv1[2], sv0[2], sv1[2], sjv[2];
#pragma unroll
            for (int k2 = 0; k2 < 2; k2++) {
                int idx = cb2 + (hb * 2 + k2) * 4;   // ks*8 floats = 4 float2
                gv0[k2] = __ldcs(&gr0[idx]);
                gv1[k2] = __ldcs(&gr1[idx]);
                sv0[k2] = __ldcs(&sr0[idx]);
                sv1[k2] = __ldcs(&sr1[idx]);
                sjv[k2] = __ldg(&sjp[idx]);
            }
#pragma unroll
            for (int k2 = 0; k2 < 2; k2++) {
                int ks = hb * 2 + k2;
                {   // (r0, c)
                    float cmb = gv0[k2].x + sv0[k2].x;
                    float x = si0 + sjv[k2].x;
                    x = (x > 0.f) ? x : LALPHA * x;
                    float val = (cmb > 0.f) ? x * cmb : NEG_BIG;
                    float p = __expf(val - mr0);
                    l0 += p; atf[ks][0] = f2tf(p);
                }
                {   // (r1, c)
                    float cmb = gv1[k2].x + sv1[k2].x;
                    float x = si1 + sjv[k2].x;
                    x = (x > 0.f) ? x : LALPHA * x;
                    float val = (cmb > 0.f) ? x * cmb : NEG_BIG;
                    float p = __expf(val - mr1);
                    l1 += p; atf[ks][1] = f2tf(p);
                }
                {   // (r0, c+1)
                    float cmb = gv0[k2].y + sv0[k2].y;
                    float x = si0 + sjv[k2].y;
                    x = (x > 0.f) ? x : LALPHA * x;
                    float val = (cmb > 0.f) ? x * cmb : NEG_BIG;
                    float p = __expf(val - mr0);
                    l0 += p; atf[ks][2] = f2tf(p);
                }
                {   // (r1, c+1)
                    float cmb = gv1[k2].y + sv1[k2].y;
                    float x = si1 + sjv[k2].y;
                    x = (x > 0.f) ? x : LALPHA * x;
                    float val = (cmb > 0.f) ? x * cmb : NEG_BIG;
                    float p = __expf(val - mr1);
                    l1 += p; atf[ks][3] = f2tf(p);
                }
            }
        }

        __syncthreads();                    // hs staged

        // ---- GEMM: k-permuted B rows 2bk, 2bk+1 ----
        const float* hb0 = hs + (wk * 32 + 2 * bk) * HST + bn;
#pragma unroll
        for (int ks = 0; ks < 4; ks++) {
            const float* hp = hb0 + ks * 8 * HST;
#pragma unroll
            for (int nt = 0; nt < 8; nt++) {
                uint32_t b0 = __float_as_uint(hp[nt * 8]);
                uint32_t b1 = __float_as_uint(hp[HST + nt * 8]);
                mma_tf32(acc[nt], atf[ks][0], atf[ks][1], atf[ks][2], atf[ks][3], b0, b1);
            }
        }
    }

    // ---- reduce partial accs across the 4 k-warps via smem ----
    __syncthreads();                        // last GEMM done; hs reusable
    float* red = smem;                      // [4][32][RST], 8704 floats exactly

#pragma unroll
    for (int nt = 0; nt < 8; nt++) {
        int c = nt * 8 + 2 * ac;
        *(float2*)&red[((wk * 32) + m0 + ar) * RST + c]     = make_float2(acc[nt][0], acc[nt][1]);
        *(float2*)&red[((wk * 32) + m0 + ar + 8) * RST + c] = make_float2(acc[nt][2], acc[nt][3]);
    }
    l0 += __shfl_down_sync(0xffffffffu, l0, 2, 4);
    l0 += __shfl_down_sync(0xffffffffu, l0, 1, 4);
    l1 += __shfl_down_sync(0xffffffffu, l1, 2, 4);
    l1 += __shfl_down_sync(0xffffffffu, l1, 1, 4);
    if (ac == 0) {
        lred[wk * 32 + m0 + ar]     = l0;
        lred[wk * 32 + m0 + ar + 8] = l1;
    }
    __syncthreads();

    int rl = t >> 3;
    int c0 = (t & 7) * 8;
    float4 a0 = make_float4(0.f, 0.f, 0.f, 0.f);
    float4 a1 = make_float4(0.f, 0.f, 0.f, 0.f);
#pragma unroll
    for (int w4 = 0; w4 < 4; w4++) {
        const float* b = &red[(w4 * 32 + rl) * RST + c0];
        float4 v0 = *(const float4*)b;
        float4 v1 = *(const float4*)(b + 4);
        a0.x += v0.x; a0.y += v0.y; a0.z += v0.z; a0.w += v0.w;
        a1.x += v1.x; a1.y += v1.y; a1.z += v1.z; a1.w += v1.w;
    }
    float* pout = g_pacc + (size_t)bid * BI * OUTF + rl * OUTF + c0;
    *(float4*)pout       = a0;
    *(float4*)(pout + 4) = a1;
    if ((t & 7) == 0) {
        float l = lred[rl] + lred[32 + rl] + lred[64 + rl] + lred[96 + rl];
        g_pl[(size_t)bid * BI + rl] = l;
    }
}

// ---------------------------------------------------------------------------
// K3: combine j-split partials, normalize, ELU
// ---------------------------------------------------------------------------
__global__ void __launch_bounds__(256) k_fin(float* __restrict__ out) {
    int t = threadIdx.x;
    int i = blockIdx.x * 64 + (t >> 2);
    int f0 = (t & 3) * 16;
    int tile = i >> 5;
    int r = i & 31;
    const float* pa = g_pacc + (size_t)(2 * tile) * BI * OUTF + r * OUTF + f0;
    const float* pb = pa + BI * OUTF;
    float l = g_pl[(size_t)(2 * tile) * BI + r] + g_pl[(size_t)(2 * tile + 1) * BI + r];
    float inv = 1.f / l;
#pragma unroll
    for (int c4 = 0; c4 < 4; c4++) {
        float4 a4 = *(const float4*)(pa + c4 * 4);
        float4 b4 = *(const float4*)(pb + c4 * 4);
        float4 o;
        float v;
        v = (a4.x + b4.x) * inv; o.x = (v > 0.f) ? v : expm1f(v);
        v = (a4.y + b4.y) * inv; o.y = (v > 0.f) ? v : expm1f(v);
        v = (a4.z + b4.z) * inv; o.z = (v > 0.f) ? v : expm1f(v);
        v = (a4.w + b4.w) * inv; o.w = (v > 0.f) ? v : expm1f(v);
        *(float4*)(out + (size_t)i * OUTF + f0 + c4 * 4) = o;
    }
}

// ---------------------------------------------------------------------------
extern "C" void kernel_launch(void* const* d_in, const int* in_sizes, int n_in,
                              void* d_out, int out_size) {
    const float* geo  = (const float*)d_in[0];
    const float* sem  = (const float*)d_in[1];
    const float* feat = (const float*)d_in[2];
    const float* W    = (const float*)d_in[3];
    const float* avec = (const float*)d_in[4];
    float* out = (float*)d_out;

    k_h<<<Nn / 32, 256>>>(feat, W, avec);

    cudaFuncSetAttribute(k_main, cudaFuncAttributeMaxDynamicSharedMemorySize, SMEM_BYTES);
    k_main<<<(Nn / BI) * JS, TPB, SMEM_BYTES>>>(geo, sem);

    k_fin<<<Nn / 64, 256>>>(out);
}

// round 9
// speedup vs baseline: 1.1381x; 1.1381x over previous
#include <cuda_runtime.h>
#include <math.h>
#include <stdint.h>

#define Nn 8192
#define IN_FEAT 128
#define OUTF 64
#define LALPHA 0.2f
#define NEG_BIG (-9e15f)

#define BI 32          // rows per CTA
#define BJ 128         // j-chunk
#define NCH (Nn/BJ)    // 64 chunks
#define TPB 256
#define HST 72         // hs stride; 72 % 32 == 8 -> B-frag LDS conflict-free
#define PST 132        // ps stride; 132 % 32 == 4 -> A-frag LDS conflict-free
#define SMEM_BYTES ((2*BJ*HST + 2*BI*PST)*4)   // 107520 B -> 2 CTAs/SM

// Scratch (device globals — no allocation allowed)
__device__ float g_htf[Nn*OUTF];     // h pre-rounded to tf32
__device__ float g_si[Nn];
__device__ float g_sj[Nn];
__device__ unsigned g_sjmax_enc;     // order-preserving encoding

__device__ __forceinline__ uint32_t f2tf(float x) {
    uint32_t r;
    asm("cvt.rna.tf32.f32 %0, %1;" : "=r"(r) : "f"(x));
    return r;
}
__device__ __forceinline__ unsigned enc_f(float x) {
    unsigned u = __float_as_uint(x);
    return (u & 0x80000000u) ? ~u : (u | 0x80000000u);
}
__device__ __forceinline__ float dec_f(unsigned u) {
    return __uint_as_float((u & 0x80000000u) ? (u & 0x7FFFFFFFu) : ~u);
}
__device__ __forceinline__ void mma_tf32(float* c,
                                         uint32_t a0, uint32_t a1, uint32_t a2, uint32_t a3,
                                         uint32_t b0, uint32_t b1) {
    asm volatile(
        "mma.sync.aligned.m16n8k8.row.col.f32.tf32.tf32.f32 "
        "{%0,%1,%2,%3}, {%4,%5,%6,%7}, {%8,%9}, {%0,%1,%2,%3};"
        : "+f"(c[0]), "+f"(c[1]), "+f"(c[2]), "+f"(c[3])
        : "r"(a0), "r"(a1), "r"(a2), "r"(a3), "r"(b0), "r"(b1));
}
__device__ __forceinline__ void cp16(uint32_t dst_smem, const void* src) {
    asm volatile("cp.async.cg.shared.global [%0], [%1], 16;" :: "r"(dst_smem), "l"(src));
}

// ---------------------------------------------------------------------------
// K1: h = features @ W.T (stored tf32-rounded), fused s_i/s_j + max(s_j)
// ---------------------------------------------------------------------------
__global__ void __launch_bounds__(256) k_h(const float* __restrict__ feat,
                                           const float* __restrict__ W,
                                           const float* __restrict__ avec) {
    __shared__ float Wt[IN_FEAT][OUTF];
    __shared__ float sjred[32];
    int t = threadIdx.x;
#pragma unroll
    for (int w = 0; w < 8; w++) {
        int idx = t + 256 * w;
        int f   = idx >> 5;
        int c4  = idx & 31;
        float4 wv = ((const float4*)W)[idx];
        int k = c4 * 4;
        Wt[k + 0][f] = wv.x;
        Wt[k + 1][f] = wv.y;
        Wt[k + 2][f] = wv.z;
        Wt[k + 3][f] = wv.w;
    }
    __syncthreads();

    int il = t >> 3;
    int fo = t & 7;
    int i  = blockIdx.x * 32 + il;
    const float4* fr = (const float4*)(feat + (size_t)i * IN_FEAT);

    float acc[8];
#pragma unroll
    for (int c = 0; c < 8; c++) acc[c] = 0.f;

#pragma unroll
    for (int kk = 0; kk < 32; kk++) {
        float4 fv = fr[kk];
#pragma unroll
        for (int c = 0; c < 4; c++) {
            float fc = (c == 0) ? fv.x : (c == 1) ? fv.y : (c == 2) ? fv.z : fv.w;
            int k = kk * 4 + c;
            float4 w0 = *(const float4*)&Wt[k][fo * 8];
            float4 w1 = *(const float4*)&Wt[k][fo * 8 + 4];
            acc[0] += fc * w0.x; acc[1] += fc * w0.y;
            acc[2] += fc * w0.z; acc[3] += fc * w0.w;
            acc[4] += fc * w1.x; acc[5] += fc * w1.y;
            acc[6] += fc * w1.z; acc[7] += fc * w1.w;
        }
    }
    uint4 o0, o1;
    o0.x = f2tf(acc[0]); o0.y = f2tf(acc[1]); o0.z = f2tf(acc[2]); o0.w = f2tf(acc[3]);
    o1.x = f2tf(acc[4]); o1.y = f2tf(acc[5]); o1.z = f2tf(acc[6]); o1.w = f2tf(acc[7]);
    *(uint4*)(g_htf + (size_t)i * OUTF + fo * 8)     = o0;
    *(uint4*)(g_htf + (size_t)i * OUTF + fo * 8 + 4) = o1;

    float sx = 0.f, sy = 0.f;
#pragma unroll
    for (int c = 0; c < 8; c++) {
        sx += acc[c] * avec[fo * 8 + c];
        sy += acc[c] * avec[OUTF + fo * 8 + c];
    }
#pragma unroll
    for (int o = 4; o > 0; o >>= 1) {
        sx += __shfl_down_sync(0xffffffffu, sx, o, 8);
        sy += __shfl_down_sync(0xffffffffu, sy, o, 8);
    }
    if (fo == 0) {
        g_si[i] = sx;
        g_sj[i] = sy;
        sjred[il] = sy;
    }
    __syncthreads();
    if (t == 0) {
        float m = sjred[0];
#pragma unroll
        for (int c = 1; c < 32; c++) m = fmaxf(m, sjred[c]);
        atomicMax(&g_sjmax_enc, enc_f(m));   // idempotent across replays
    }
}

// ---------------------------------------------------------------------------
// K2: fused scores + single-pass softmax + tf32 MMA P@H + ELU.
// Full double buffering (hs AND ps) -> ONE sync per chunk; h staged by
// cp.async (waited only at the sync); s_j read via __ldg.
// Grid: 256 CTAs x 256 threads, 2 CTAs/SM.
// ---------------------------------------------------------------------------
__global__ void __launch_bounds__(TPB, 2) k_main(const float* __restrict__ geo,
                                                 const float* __restrict__ sem,
                                                 float* __restrict__ out) {
    extern __shared__ float smem[];
    float* hsb[2] = { smem, smem + BJ * HST };
    float* psb[2] = { smem + 2 * BJ * HST, smem + 2 * BJ * HST + BI * PST };
    __shared__ float lfin[BI];

    int t    = threadIdx.x;
    int i0   = blockIdx.x * BI;
    int lane = t & 31;
    int warp = t >> 5;

    // ---- score mapping: 8 threads/row ----
    int r = t >> 3;
    int q = t & 7;
    float si_r  = g_si[i0 + r];
    float m_r   = fmaxf(0.f, 2.f * (si_r + dec_f(g_sjmax_enc)));
    float l_acc = 0.f;
    const float4* gbase = (const float4*)(geo + (size_t)(i0 + r) * Nn);
    const float4* sbase = (const float4*)(sem + (size_t)(i0 + r) * Nn);
    const float4* sjb   = (const float4*)g_sj;

    // ---- staging mapping ----
    int jr = t >> 4, f4 = t & 15;

    // ---- gemm mapping: 8 warps = 2(m) x 4(n), warp tile m16 x n16 ----
    int wm = warp & 1, wn = warp >> 1;
    int m0 = wm * 16, n0 = wn * 16;
    int ar = lane >> 2, ac = lane & 3;
    int bk = lane & 3,  bn = lane >> 2;

    float acc[2][4];
#pragma unroll
    for (int a = 0; a < 2; a++)
#pragma unroll
        for (int b = 0; b < 4; b++) acc[a][b] = 0.f;

    float4 gv[4], sv[4];

    // ============ prologue: chunk 0 ============
#pragma unroll
    for (int kk = 0; kk < 4; kk++) {           // adj chunk 0
        gv[kk] = __ldcs(&gbase[q + 8 * kk]);
        sv[kk] = __ldcs(&sbase[q + 8 * kk]);
    }
    {   // stage hs[0] <- h chunk 0 via cp.async
        uint32_t hs_s = (uint32_t)__cvta_generic_to_shared(hsb[0]);
#pragma unroll
        for (int it = 0; it < 8; it++) {
            int j = jr + 16 * it;
            cp16(hs_s + (j * HST + f4 * 4) * 4, g_htf + (size_t)j * OUTF + f4 * 4);
        }
        asm volatile("cp.async.commit_group;");
    }
    {   // scores chunk 0 -> ps[0]
#pragma unroll
        for (int kk = 0; kk < 4; kk++) {
            int f4i = q + 8 * kk;
            int j0l = f4i * 4;
            float4 g4 = gv[kk], s4 = sv[kk];
            float4 sj4 = __ldg(&sjb[f4i]);
            uint4 po;
            uint32_t* pd = (uint32_t*)&po;
#pragma unroll
            for (int c = 0; c < 4; c++) {
                float g = (c == 0) ? g4.x : (c == 1) ? g4.y : (c == 2) ? g4.z : g4.w;
                float s = (c == 0) ? s4.x : (c == 1) ? s4.y : (c == 2) ? s4.z : s4.w;
                float sj = (c == 0) ? sj4.x : (c == 1) ? sj4.y : (c == 2) ? sj4.z : sj4.w;
                float cmb = g + s;
                float x = si_r + sj;
                x = (x > 0.f) ? x : LALPHA * x;
                float val = (cmb > 0.f) ? x * cmb : NEG_BIG;
                float p = __expf(val - m_r);
                l_acc += p;
                pd[c] = f2tf(p);
            }
            *(uint4*)(psb[0] + r * PST + j0l) = po;
        }
    }
#pragma unroll
    for (int kk = 0; kk < 4; kk++) {           // adj chunk 1
        gv[kk] = __ldcs(&gbase[32 + q + 8 * kk]);
        sv[kk] = __ldcs(&sbase[32 + q + 8 * kk]);
    }
    asm volatile("cp.async.wait_group 0;");
    __syncthreads();

    // ============ main loop: 1 sync per chunk ============
    for (int ci = 0; ci < NCH; ci++) {
        int b = ci & 1;

        if (ci + 1 < NCH) {
            int jn = (ci + 1) * BJ;
            // stage hs[b^1] <- h chunk ci+1 (async)
            uint32_t hs_s = (uint32_t)__cvta_generic_to_shared(hsb[b ^ 1]);
#pragma unroll
            for (int it = 0; it < 8; it++) {
                int j = jr + 16 * it;
                cp16(hs_s + (j * HST + f4 * 4) * 4,
                     g_htf + (size_t)(jn + j) * OUTF + f4 * 4);
            }
            asm volatile("cp.async.commit_group;");

            // scores chunk ci+1 -> ps[b^1] (adj regs prefetched last iter)
            int cb4 = jn >> 2;
#pragma unroll
            for (int kk = 0; kk < 4; kk++) {
                int f4i = q + 8 * kk;
                int j0l = f4i * 4;
                float4 g4 = gv[kk], s4 = sv[kk];
                float4 sj4 = __ldg(&sjb[cb4 + f4i]);
                uint4 po;
                uint32_t* pd = (uint32_t*)&po;
#pragma unroll
                for (int c = 0; c < 4; c++) {
                    float g = (c == 0) ? g4.x : (c == 1) ? g4.y : (c == 2) ? g4.z : g4.w;
                    float s = (c == 0) ? s4.x : (c == 1) ? s4.y : (c == 2) ? s4.z : s4.w;
                    float sj = (c == 0) ? sj4.x : (c == 1) ? sj4.y : (c == 2) ? sj4.z : sj4.w;
                    float cmb = g + s;
                    float x = si_r + sj;
                    x = (x > 0.f) ? x : LALPHA * x;
                    float val = (cmb > 0.f) ? x * cmb : NEG_BIG;
                    float p = __expf(val - m_r);
                    l_acc += p;
                    pd[c] = f2tf(p);
                }
                *(uint4*)(psb[b ^ 1] + r * PST + j0l) = po;
            }

            // prefetch adj chunk ci+2
            int jp = ci + 2 < NCH ? (ci + 2) * BJ : 0;
            int jb4 = jp >> 2;
#pragma unroll
            for (int kk = 0; kk < 4; kk++) {
                gv[kk] = __ldcs(&gbase[jb4 + q + 8 * kk]);
                sv[kk] = __ldcs(&sbase[jb4 + q + 8 * kk]);
            }
        }

        // GEMM chunk ci from hs[b], ps[b]
        const float* psA = psb[b] + (m0 + ar) * PST + ac;
        const float* hsB = hsb[b] + bk * HST + n0 + bn;
#pragma unroll
        for (int ks = 0; ks < 16; ks++) {
            int k0 = ks * 8;
            uint32_t a0 = __float_as_uint(psA[k0]);
            uint32_t a1 = __float_as_uint(psA[8 * PST + k0]);
            uint32_t a2 = __float_as_uint(psA[k0 + 4]);
            uint32_t a3 = __float_as_uint(psA[8 * PST + k0 + 4]);
#pragma unroll
            for (int nt = 0; nt < 2; nt++) {
                uint32_t b0 = __float_as_uint(hsB[k0 * HST + nt * 8]);
                uint32_t b1 = __float_as_uint(hsB[(k0 + 4) * HST + nt * 8]);
                mma_tf32(acc[nt], a0, a1, a2, a3, b0, b1);
            }
        }

        asm volatile("cp.async.wait_group 0;");
        __syncthreads();
    }

    // ---- reduce l across the 8 threads of each row ----
#pragma unroll
    for (int o = 4; o > 0; o >>= 1)
        l_acc += __shfl_down_sync(0xffffffffu, l_acc, o, 8);
    if (q == 0) lfin[r] = l_acc;
    __syncthreads();

    // ---- epilogue: out = elu(acc / l) ----
    int row0 = m0 + (lane >> 2);
    int col0 = 2 * (lane & 3);
    float inv0 = 1.f / lfin[row0];
    float inv1 = 1.f / lfin[row0 + 8];
#pragma unroll
    for (int nt = 0; nt < 2; nt++) {
        int col = n0 + nt * 8 + col0;
        float v0 = acc[nt][0] * inv0;
        float v1 = acc[nt][1] * inv0;
        float v2 = acc[nt][2] * inv1;
        float v3 = acc[nt][3] * inv1;
        float2 o01, o23;
        o01.x = (v0 > 0.f) ? v0 : expm1f(v0);
        o01.y = (v1 > 0.f) ? v1 : expm1f(v1);
        o23.x = (v2 > 0.f) ? v2 : expm1f(v2);
        o23.y = (v3 > 0.f) ? v3 : expm1f(v3);
        *(float2*)(out + (size_t)(i0 + row0) * OUTF + col)     = o01;
        *(float2*)(out + (size_t)(i0 + row0 + 8) * OUTF + col) = o23;
    }
}

// ---------------------------------------------------------------------------
extern "C" void kernel_launch(void* const* d_in, const int* in_sizes, int n_in,
                              void* d_out, int out_size) {
    const float* geo  = (const float*)d_in[0];
    const float* sem  = (const float*)d_in[1];
    const float* feat = (const float*)d_in[2];
    const float* W    = (const float*)d_in[3];
    const float* avec = (const float*)d_in[4];
    float* out = (float*)d_out;

    k_h<<<Nn / 32, 256>>>(feat, W, avec);

    cudaFuncSetAttribute(k_main, cudaFuncAttributeMaxDynamicSharedMemorySize, SMEM_BYTES);
    k_main<<<Nn / BI, TPB, SMEM_BYTES>>>(geo, sem, out);
}

// round 10
// speedup vs baseline: 1.6610x; 1.4594x over previous
#include <cuda_runtime.h>
#include <math.h>
#include <stdint.h>

#define Nn 8192
#define IN_FEAT 128
#define OUTF 64
#define LALPHA 0.2f
#define NEG_BIG (-9e15f)

#define BI 32              // rows per tile
#define BJ 64              // j-chunk (halved vs R3 -> fewer regs, less smem)
#define JS 2               // j-split CTAs per tile
#define NCH ((Nn/JS)/BJ)   // 64 chunks per CTA
#define TPB 256
#define HST 72             // hs stride; 72 % 32 == 8 -> B-frag LDS conflict-free
#define PST 68             // ps stride; 68 % 32 == 4 -> A-frag LDS conflict-free
#define SMEM_BYTES ((2*BJ*HST + BI*PST)*4)   // 45568 B -> 3 CTAs/SM

// Scratch (device globals — no allocation allowed)
__device__ float g_htf[Nn*OUTF];               // h pre-rounded to tf32
__device__ float g_si[Nn];
__device__ float g_sj[Nn];
__device__ unsigned g_sjmax_enc;               // order-preserving encoding
__device__ float g_pacc[(Nn/BI)*JS*BI*OUTF];   // partial P@H per split CTA
__device__ float g_pl[(Nn/BI)*JS*BI];          // partial row sums

__device__ __forceinline__ uint32_t f2tf(float x) {
    uint32_t r;
    asm("cvt.rna.tf32.f32 %0, %1;" : "=r"(r) : "f"(x));
    return r;
}
__device__ __forceinline__ unsigned enc_f(float x) {
    unsigned u = __float_as_uint(x);
    return (u & 0x80000000u) ? ~u : (u | 0x80000000u);
}
__device__ __forceinline__ float dec_f(unsigned u) {
    return __uint_as_float((u & 0x80000000u) ? (u & 0x7FFFFFFFu) : ~u);
}
__device__ __forceinline__ void mma_tf32(float* c,
                                         uint32_t a0, uint32_t a1, uint32_t a2, uint32_t a3,
                                         uint32_t b0, uint32_t b1) {
    asm volatile(
        "mma.sync.aligned.m16n8k8.row.col.f32.tf32.tf32.f32 "
        "{%0,%1,%2,%3}, {%4,%5,%6,%7}, {%8,%9}, {%0,%1,%2,%3};"
        : "+f"(c[0]), "+f"(c[1]), "+f"(c[2]), "+f"(c[3])
        : "r"(a0), "r"(a1), "r"(a2), "r"(a3), "r"(b0), "r"(b1));
}

// ---------------------------------------------------------------------------
// K1: h = features @ W.T (stored tf32-rounded), fused s_i/s_j + max(s_j)
// ---------------------------------------------------------------------------
__global__ void __launch_bounds__(256) k_h(const float* __restrict__ feat,
                                           const float* __restrict__ W,
                                           const float* __restrict__ avec) {
    __shared__ float Wt[IN_FEAT][OUTF];
    __shared__ float sjred[32];
    int t = threadIdx.x;
#pragma unroll
    for (int w = 0; w < 8; w++) {
        int idx = t + 256 * w;
        int f   = idx >> 5;
        int c4  = idx & 31;
        float4 wv = ((const float4*)W)[idx];
        int k = c4 * 4;
        Wt[k + 0][f] = wv.x;
        Wt[k + 1][f] = wv.y;
        Wt[k + 2][f] = wv.z;
        Wt[k + 3][f] = wv.w;
    }
    __syncthreads();

    int il = t >> 3;
    int fo = t & 7;
    int i  = blockIdx.x * 32 + il;
    const float4* fr = (const float4*)(feat + (size_t)i * IN_FEAT);

    float acc[8];
#pragma unroll
    for (int c = 0; c < 8; c++) acc[c] = 0.f;

#pragma unroll
    for (int kk = 0; kk < 32; kk++) {
        float4 fv = fr[kk];
#pragma unroll
        for (int c = 0; c < 4; c++) {
            float fc = (c == 0) ? fv.x : (c == 1) ? fv.y : (c == 2) ? fv.z : fv.w;
            int k = kk * 4 + c;
            float4 w0 = *(const float4*)&Wt[k][fo * 8];
            float4 w1 = *(const float4*)&Wt[k][fo * 8 + 4];
            acc[0] += fc * w0.x; acc[1] += fc * w0.y;
            acc[2] += fc * w0.z; acc[3] += fc * w0.w;
            acc[4] += fc * w1.x; acc[5] += fc * w1.y;
            acc[6] += fc * w1.z; acc[7] += fc * w1.w;
        }
    }
    uint4 o0, o1;
    o0.x = f2tf(acc[0]); o0.y = f2tf(acc[1]); o0.z = f2tf(acc[2]); o0.w = f2tf(acc[3]);
    o1.x = f2tf(acc[4]); o1.y = f2tf(acc[5]); o1.z = f2tf(acc[6]); o1.w = f2tf(acc[7]);
    *(uint4*)(g_htf + (size_t)i * OUTF + fo * 8)     = o0;
    *(uint4*)(g_htf + (size_t)i * OUTF + fo * 8 + 4) = o1;

    float sx = 0.f, sy = 0.f;
#pragma unroll
    for (int c = 0; c < 8; c++) {
        sx += acc[c] * avec[fo * 8 + c];
        sy += acc[c] * avec[OUTF + fo * 8 + c];
    }
#pragma unroll
    for (int o = 4; o > 0; o >>= 1) {
        sx += __shfl_down_sync(0xffffffffu, sx, o, 8);
        sy += __shfl_down_sync(0xffffffffu, sy, o, 8);
    }
    if (fo == 0) {
        g_si[i] = sx;
        g_sj[i] = sy;
        sjred[il] = sy;
    }
    __syncthreads();
    if (t == 0) {
        float m = sjred[0];
#pragma unroll
        for (int c = 1; c < 32; c++) m = fmaxf(m, sjred[c]);
        atomicMax(&g_sjmax_enc, enc_f(m));   // idempotent across replays
    }
}

// ---------------------------------------------------------------------------
// K2: R3 structure exactly (double hs, single ps, 2 syncs/chunk), but BJ=64
//     + JS=2 j-split -> 45.6 KB smem, 3 CTAs/SM, grid 512.
// ---------------------------------------------------------------------------
__global__ void __launch_bounds__(TPB, 3) k_main(const float* __restrict__ geo,
                                                 const float* __restrict__ sem) {
    extern __shared__ float smem[];
    float* hs0 = smem;                       // [BJ][HST] tf32 h chunk, buf 0
    float* hs1 = smem + BJ * HST;            // buf 1
    float* ps  = smem + 2 * BJ * HST;        // [BI][PST] tf32 p tile

    int t     = threadIdx.x;
    int bid   = blockIdx.x;
    int tile  = bid >> 1;
    int half  = bid & 1;
    int i0    = tile * BI;
    int jbase = half * (Nn / JS);
    int lane  = t & 31;
    int warp  = t >> 5;

    // ---- score mapping: 8 threads/row ----
    int r = t >> 3;
    int q = t & 7;
    float si_r  = g_si[i0 + r];
    float m_r   = fmaxf(0.f, 2.f * (si_r + dec_f(g_sjmax_enc)));
    float l_acc = 0.f;
    const float4* gbase = (const float4*)(geo + (size_t)(i0 + r) * Nn + jbase);
    const float4* sbase = (const float4*)(sem + (size_t)(i0 + r) * Nn + jbase);
    const float4* sjb   = (const float4*)(g_sj + jbase);

    // ---- staging mapping ----
    int jr = t >> 4, f4 = t & 15;

    // ---- gemm mapping: 8 warps = 2(m) x 4(n), warp tile m16 x n16 ----
    int wm = warp & 1, wn = warp >> 1;
    int m0 = wm * 16, n0 = wn * 16;
    int ar = lane >> 2, ac = lane & 3;
    int bk = lane & 3,  bn = lane >> 2;

    float acc[2][4];
#pragma unroll
    for (int a = 0; a < 2; a++)
#pragma unroll
        for (int b = 0; b < 4; b++) acc[a][b] = 0.f;

    // prefetch adjacency chunk 0 (2 float4 per matrix per thread)
    float4 gv[2], sv[2];
#pragma unroll
    for (int kk = 0; kk < 2; kk++) {
        gv[kk] = __ldcs(&gbase[q + 8 * kk]);
        sv[kk] = __ldcs(&sbase[q + 8 * kk]);
    }

    int buf = 0;
    for (int ci = 0; ci < NCH; ci++, buf ^= 1) {
        float* hs = buf ? hs1 : hs0;

        // ---- stage h chunk (tf32 already): 64 rows x 16 float4 ----
        int jrow = jbase + ci * BJ;
#pragma unroll
        for (int it = 0; it < 4; it++) {
            int j = jr + 16 * it;
            float4 hv = *(const float4*)(g_htf + (size_t)(jrow + j) * OUTF + f4 * 4);
            *(float4*)(hs + j * HST + f4 * 4) = hv;
        }

        __syncthreads();   // hs[buf] staged; GEMM(ci-1) done reading ps

        // ---- scores -> p = exp(val - m_r), tf32, row-major ps[r][j] ----
        int cb4 = ci * (BJ / 4);
#pragma unroll
        for (int kk = 0; kk < 2; kk++) {
            int f4i = q + 8 * kk;
            int j0l = f4i * 4;
            float4 g4 = gv[kk], s4 = sv[kk];
            float4 sj4 = __ldg(&sjb[cb4 + f4i]);
            uint4 po;
            uint32_t* pd = (uint32_t*)&po;
#pragma unroll
            for (int c = 0; c < 4; c++) {
                float g = (c == 0) ? g4.x : (c == 1) ? g4.y : (c == 2) ? g4.z : g4.w;
                float s = (c == 0) ? s4.x : (c == 1) ? s4.y : (c == 2) ? s4.z : s4.w;
                float sj = (c == 0) ? sj4.x : (c == 1) ? sj4.y : (c == 2) ? sj4.z : sj4.w;
                float cmb = g + s;
                float x = si_r + sj;
                x = (x > 0.f) ? x : LALPHA * x;
                float val = (cmb > 0.f) ? x * cmb : NEG_BIG;
                float p = __expf(val - m_r);
                l_acc += p;
                pd[c] = f2tf(p);
            }
            *(uint4*)(ps + r * PST + j0l) = po;
        }

        // ---- prefetch next adjacency chunk (lands during GEMM) ----
        int cn4 = (ci + 1 < NCH) ? (ci + 1) * (BJ / 4) : 0;
#pragma unroll
        for (int kk = 0; kk < 2; kk++) {
            gv[kk] = __ldcs(&gbase[cn4 + q + 8 * kk]);
            sv[kk] = __ldcs(&sbase[cn4 + q + 8 * kk]);
        }

        __syncthreads();   // ps ready

        // ---- tensor-core GEMM: acc += P[32,64] @ H[64,64] ----
        const float* psA = ps + (m0 + ar) * PST + ac;
        const float* hsB = hs + bk * HST + n0 + bn;
#pragma unroll
        for (int ks = 0; ks < 8; ks++) {
            int k0 = ks * 8;
            uint32_t a0 = __float_as_uint(psA[k0]);
            uint32_t a1 = __float_as_uint(psA[8 * PST + k0]);
            uint32_t a2 = __float_as_uint(psA[k0 + 4]);
            uint32_t a3 = __float_as_uint(psA[8 * PST + k0 + 4]);
#pragma unroll
            for (int nt = 0; nt < 2; nt++) {
                uint32_t b0 = __float_as_uint(hsB[k0 * HST + nt * 8]);
                uint32_t b1 = __float_as_uint(hsB[(k0 + 4) * HST + nt * 8]);
                mma_tf32(acc[nt], a0, a1, a2, a3, b0, b1);
            }
        }
    }

    // ---- partial l: reduce across the 8 threads of each row ----
#pragma unroll
    for (int o = 4; o > 0; o >>= 1)
        l_acc += __shfl_down_sync(0xffffffffu, l_acc, o, 8);
    if (q == 0) g_pl[(size_t)bid * BI + r] = l_acc;

    // ---- partial acc -> global (unnormalized; exact since m_r is global) ----
    float* pout = g_pacc + (size_t)bid * BI * OUTF;
    int row0 = m0 + (lane >> 2);
    int col0 = 2 * (lane & 3);
#pragma unroll
    for (int nt = 0; nt < 2; nt++) {
        int col = n0 + nt * 8 + col0;
        *(float2*)(pout + row0 * OUTF + col)       = make_float2(acc[nt][0], acc[nt][1]);
        *(float2*)(pout + (row0 + 8) * OUTF + col) = make_float2(acc[nt][2], acc[nt][3]);
    }
}

// ---------------------------------------------------------------------------
// K3: combine j-split partials, normalize, ELU
// ---------------------------------------------------------------------------
__global__ void __launch_bounds__(256) k_fin(float* __restrict__ out) {
    int t = threadIdx.x;
    int i = blockIdx.x * 64 + (t >> 2);
    int f0 = (t & 3) * 16;
    int tile = i >> 5;
    int r = i & 31;
    const float* pa = g_pacc + (size_t)(2 * tile) * BI * OUTF + r * OUTF + f0;
    const float* pb = pa + BI * OUTF;
    float l = g_pl[(size_t)(2 * tile) * BI + r] + g_pl[(size_t)(2 * tile + 1) * BI + r];
    float inv = 1.f / l;
#pragma unroll
    for (int c4 = 0; c4 < 4; c4++) {
        float4 a4 = *(const float4*)(pa + c4 * 4);
        float4 b4 = *(const float4*)(pb + c4 * 4);
        float4 o;
        float v;
        v = (a4.x + b4.x) * inv; o.x = (v > 0.f) ? v : expm1f(v);
        v = (a4.y + b4.y) * inv; o.y = (v > 0.f) ? v : expm1f(v);
        v = (a4.z + b4.z) * inv; o.z = (v > 0.f) ? v : expm1f(v);
        v = (a4.w + b4.w) * inv; o.w = (v > 0.f) ? v : expm1f(v);
        *(float4*)(out + (size_t)i * OUTF + f0 + c4 * 4) = o;
    }
}

// ---------------------------------------------------------------------------
extern "C" void kernel_launch(void* const* d_in, const int* in_sizes, int n_in,
                              void* d_out, int out_size) {
    const float* geo  = (const float*)d_in[0];
    const float* sem  = (const float*)d_in[1];
    const float* feat = (const float*)d_in[2];
    const float* W    = (const float*)d_in[3];
    const float* avec = (const float*)d_in[4];
    float* out = (float*)d_out;

    k_h<<<Nn / 32, 256>>>(feat, W, avec);

    cudaFuncSetAttribute(k_main, cudaFuncAttributeMaxDynamicSharedMemorySize, SMEM_BYTES);
    k_main<<<(Nn / BI) * JS, TPB, SMEM_BYTES>>>(geo, sem);

    k_fin<<<Nn / 64, 256>>>(out);
}